// round 10
// baseline (speedup 1.0000x reference)
#include <cuda_runtime.h>
#include <cuda_fp16.h>

#define TAGSETN 64
#define SEQN    512
#define MIDT    256
#define NTAGS   66
#define STARTS  64
#define STOPS   65
#define LOG2E_F 1.4426950408889634f
#define LN2_F   0.6931471805599453f
#define OFFB    12.0f
#define GB      4

__device__ __forceinline__ float ex2f(float x){float r;asm("ex2.approx.ftz.f32 %0, %1;":"=f"(r):"f"(x));return r;}
__device__ __forceinline__ float lg2f(float x){float r;asm("lg2.approx.ftz.f32 %0, %1;":"=f"(r):"f"(x));return r;}
__device__ __forceinline__ unsigned swz(unsigned off){ return off ^ ((off >> 3) & 0x70u); }

__device__ __forceinline__ void mma16816(float d[4], const unsigned a[4], const unsigned b[2],
                                         float c0, float c1, float c2, float c3) {
    asm volatile("mma.sync.aligned.m16n8k16.row.col.f32.f16.f16.f32 "
                 "{%0,%1,%2,%3}, {%4,%5,%6,%7}, {%8,%9}, {%10,%11,%12,%13};"
                 : "=f"(d[0]), "=f"(d[1]), "=f"(d[2]), "=f"(d[3])
                 : "r"(a[0]), "r"(a[1]), "r"(a[2]), "r"(a[3]), "r"(b[0]), "r"(b[1]),
                   "f"(c0), "f"(c1), "f"(c2), "f"(c3));
}
__device__ __forceinline__ void ldmx4(unsigned a[4], unsigned addr) {
    asm volatile("ldmatrix.sync.aligned.m8n8.x4.shared.b16 {%0,%1,%2,%3}, [%4];"
                 : "=r"(a[0]), "=r"(a[1]), "=r"(a[2]), "=r"(a[3]) : "r"(addr));
}

__global__ __launch_bounds__(64)
void crf_mma_kernel(const float* __restrict__ em,
                    const int*   __restrict__ tags,
                    const float* __restrict__ trans,
                    float*       __restrict__ out)
{
    __shared__ __align__(128) __half bufF[2][16 * 64];
    __shared__ __align__(128) __half bufB[2][16 * 64];
    __shared__ float lgA[GB][TAGSETN], lgB[GB][TAGSETN];
    __shared__ int   stg[GB][SEQN];

    const int blk = blockIdx.x;
    const int tid = threadIdx.x;
    const int w   = tid >> 5;          // 0 = fwd warp, 1 = bwd warp
    const int l   = tid & 31;
    const int q   = l & 3;
    const int b   = (l >> 2) & 3;      // batch (aliased for lanes 16-31)
    const bool va = (l < 16);

    for (int idx = tid; idx < GB * SEQN; idx += 64)
        stg[idx >> 9][idx & 511] = tags[(size_t)(blk * GB + (idx >> 9)) * SEQN + (idx & 511)];
    for (int idx = tid; idx < 2 * 12 * 32; idx += 64) {   // zero A rows 4..15
        const int par = idx / (12 * 32), rem = idx % (12 * 32);
        const unsigned off = swz((unsigned)((4 + rem / 32) * 128 + (rem % 32) * 4));
        *(__half2*)((char*)&bufF[par][0] + off) = __floats2half2_rn(0.f, 0.f);
        *(__half2*)((char*)&bufB[par][0] + off) = __floats2half2_rn(0.f, 0.f);
    }
    __syncthreads();

    // B fragments: fwd B[k][n]=exp(T[k][col]); bwd B[k][n]=exp(T[col][k])
    unsigned Ef[8][4][2];
    {
        const int jn = l >> 2;
        #pragma unroll
        for (int n = 0; n < 8; ++n) {
            const int col = n * 8 + jn;
            #pragma unroll
            for (int kc = 0; kc < 4; ++kc) {
                const int k0 = kc * 16 + q * 2;
                float e00, e01, e10, e11;
                if (w == 0) {
                    e00 = __expf(trans[(k0    ) * NTAGS + col]);
                    e01 = __expf(trans[(k0 + 1) * NTAGS + col]);
                    e10 = __expf(trans[(k0 + 8) * NTAGS + col]);
                    e11 = __expf(trans[(k0 + 9) * NTAGS + col]);
                } else {
                    e00 = __expf(trans[col * NTAGS + (k0    )]);
                    e01 = __expf(trans[col * NTAGS + (k0 + 1)]);
                    e10 = __expf(trans[col * NTAGS + (k0 + 8)]);
                    e11 = __expf(trans[col * NTAGS + (k0 + 9)]);
                }
                __half2 h0 = __floats2half2_rn(e00, e01);
                __half2 h1 = __floats2half2_rn(e10, e11);
                Ef[n][kc][0] = *(unsigned*)&h0;
                Ef[n][kc][1] = *(unsigned*)&h1;
            }
        }
    }

    char* mybuf = (char*)((w == 0) ? &bufF[0][0] : &bufB[0][0]);
    const unsigned PARB  = 16 * 64 * 2;
    const unsigned abase = (unsigned)__cvta_generic_to_shared(mybuf);
    unsigned lmoff[4], stoff[8];
    #pragma unroll
    for (int kc = 0; kc < 4; ++kc)
        lmoff[kc] = swz((unsigned)((l & 15) * 128 + (l >> 4) * 16 + kc * 32));
    #pragma unroll
    for (int n = 0; n < 8; ++n)
        stoff[n] = swz((unsigned)(b * 128 + n * 16 + q * 4));

    const float* embq = em + (size_t)(blk * GB + b) * (SEQN * TAGSETN) + q * 2;

    float a[16], p[16];
    float2 eraw[8];
    float lb, Mprev, emL0 = 0.f;
    int tgc;

    if (w == 0) {
        // ================ FORWARD: alpha_0 .. alpha_256 ================
        const float Tst0 = __ldg(&trans[STARTS * NTAGS]);
        float lbv[16], mx = -1e30f;
        #pragma unroll
        for (int n = 0; n < 8; ++n) {
            const int j0 = n * 8 + q * 2;
            const float2 e0 = *(const float2*)(embq + n * 8);
            const float v0 = (e0.x + trans[STARTS * NTAGS + j0    ] - Tst0) * LOG2E_F;
            const float v1 = (e0.y + trans[STARTS * NTAGS + j0 + 1] - Tst0) * LOG2E_F;
            lbv[2*n] = v0; lbv[2*n+1] = v1;
            mx = fmaxf(mx, fmaxf(v0, v1));
        }
        mx = fmaxf(mx, __shfl_xor_sync(0xffffffffu, mx, 1));
        mx = fmaxf(mx, __shfl_xor_sync(0xffffffffu, mx, 2));
        Mprev = mx;
        #pragma unroll
        for (int k = 0; k < 16; ++k) a[k] = ex2f(lbv[k] - Mprev);
        lb = __shfl_sync(0xffffffffu, lbv[0], l & ~3);

        float el0 = 0.f;
        #pragma unroll
        for (int n = 0; n < 8; ++n) {
            const float2 e1 = *(const float2*)(embq + 1 * TAGSETN + n * 8);
            p[2*n] = ex2f(e1.x * LOG2E_F); p[2*n+1] = ex2f(e1.y * LOG2E_F);
            if (n == 0) el0 = e1.x * LOG2E_F;
            eraw[n] = *(const float2*)(embq + 2 * TAGSETN + n * 8);
        }
        emL0 = __shfl_sync(0xffffffffu, el0, l & ~3);
        tgc = stg[b][1];

        #pragma unroll 1
        for (int t = 1; t <= MIDT; ++t) {
            const unsigned pb = (unsigned)(t & 1) * PARB;
            if (va) {
                #pragma unroll
                for (int n = 0; n < 8; ++n)
                    *(__half2*)(mybuf + pb + stoff[n]) = __floats2half2_rn(a[2*n], a[2*n+1]);
            }
            __syncwarp();
            const float Mt = lb + OFFB;
            const float hb = ex2f(Mprev - Mt);

            float d[8][4]; unsigned af[4];
            #pragma unroll
            for (int kc = 0; kc < 4; ++kc) {
                ldmx4(af, abase + pb + lmoff[kc]);
                #pragma unroll
                for (int n = 0; n < 8; ++n) {
                    if (kc == 0) mma16816(d[n], af, Ef[n][0], 0.f, 0.f, 0.f, 0.f);
                    else         mma16816(d[n], af, Ef[n][kc], d[n][0], d[n][1], d[n][2], d[n][3]);
                }
            }

            const bool mk = (tgc != 0);
            const float s00 = __shfl_sync(0xffffffffu, d[0][0], l & ~3);
            lb = mk ? (emL0 + Mprev + lg2f(s00)) : lb;
            #pragma unroll
            for (int n = 0; n < 8; ++n) {
                a[2*n]   = mk ? d[n][0] * (p[2*n]   * hb) : a[2*n]   * hb;
                a[2*n+1] = mk ? d[n][1] * (p[2*n+1] * hb) : a[2*n+1] * hb;
            }
            Mprev = Mt;

            float e0n = 0.f;
            #pragma unroll
            for (int n = 0; n < 8; ++n) {
                p[2*n] = ex2f(eraw[n].x * LOG2E_F); p[2*n+1] = ex2f(eraw[n].y * LOG2E_F);
                if (n == 0) e0n = eraw[n].x * LOG2E_F;
            }
            emL0 = __shfl_sync(0xffffffffu, e0n, l & ~3);
            const int tn = (t + 2 <= MIDT) ? t + 2 : MIDT;
            #pragma unroll
            for (int n = 0; n < 8; ++n)
                eraw[n] = *(const float2*)(embq + tn * TAGSETN + n * 8);
            tgc = stg[b][(t + 1 <= MIDT) ? t + 1 : MIDT];
        }
        if (va) {
            #pragma unroll
            for (int n = 0; n < 8; ++n) {
                lgA[b][n*8 + q*2    ] = lg2f(a[2*n])   + Mprev;
                lgA[b][n*8 + q*2 + 1] = lg2f(a[2*n+1]) + Mprev;
            }
        }
    } else {
        // ================ BACKWARD: beta_511 .. beta_256 ================
        Mprev = 0.f; lb = 0.f;
        #pragma unroll
        for (int k = 0; k < 16; ++k) a[k] = 1.f;
        #pragma unroll
        for (int n = 0; n < 8; ++n) {
            const float2 e = *(const float2*)(embq + 511 * TAGSETN + n * 8);
            p[2*n] = ex2f(e.x * LOG2E_F); p[2*n+1] = ex2f(e.y * LOG2E_F);
            eraw[n] = *(const float2*)(embq + 510 * TAGSETN + n * 8);
        }
        tgc = stg[b][511];

        #pragma unroll 1
        for (int t = 511; t >= 257; --t) {
            const unsigned pb = (unsigned)(t & 1) * PARB;
            if (va) {
                #pragma unroll
                for (int n = 0; n < 8; ++n)
                    *(__half2*)(mybuf + pb + stoff[n]) =
                        __floats2half2_rn(a[2*n] * p[2*n], a[2*n+1] * p[2*n+1]);
            }
            __syncwarp();
            const float Mt = lb + OFFB;
            const float hb = ex2f(Mprev - Mt);

            float d[8][4]; unsigned af[4];
            #pragma unroll
            for (int kc = 0; kc < 4; ++kc) {
                ldmx4(af, abase + pb + lmoff[kc]);
                #pragma unroll
                for (int n = 0; n < 8; ++n) {
                    if (kc == 0) mma16816(d[n], af, Ef[n][0], 0.f, 0.f, 0.f, 0.f);
                    else         mma16816(d[n], af, Ef[n][kc], d[n][0], d[n][1], d[n][2], d[n][3]);
                }
            }

            const bool mk = (tgc != 0);
            const float s00 = __shfl_sync(0xffffffffu, d[0][0], l & ~3);
            lb = mk ? (Mprev + lg2f(s00)) : lb;
            #pragma unroll
            for (int n = 0; n < 8; ++n) {
                a[2*n]   = (mk ? d[n][0] : a[2*n])   * hb;
                a[2*n+1] = (mk ? d[n][1] : a[2*n+1]) * hb;
            }
            Mprev = Mt;

            #pragma unroll
            for (int n = 0; n < 8; ++n) {
                p[2*n] = ex2f(eraw[n].x * LOG2E_F); p[2*n+1] = ex2f(eraw[n].y * LOG2E_F);
            }
            const int tn = (t - 2 >= 257) ? t - 2 : 257;
            #pragma unroll
            for (int n = 0; n < 8; ++n)
                eraw[n] = *(const float2*)(embq + tn * TAGSETN + n * 8);
            tgc = stg[b][(t - 1 >= 257) ? t - 1 : 257];
        }
        if (va) {
            #pragma unroll
            for (int n = 0; n < 8; ++n) {
                lgB[b][n*8 + q*2    ] = lg2f(a[2*n])   + Mprev;
                lgB[b][n*8 + q*2 + 1] = lg2f(a[2*n+1]) + Mprev;
            }
        }
    }
    __syncthreads();

    // ================ combine: 16 threads per batch ================
    const int cb = tid >> 4;
    const int cr = tid & 15;
    float vv[4];
    #pragma unroll
    for (int i = 0; i < 4; ++i)
        vv[i] = lgA[cb][cr * 4 + i] + lgB[cb][cr * 4 + i];
    float mz = fmaxf(fmaxf(vv[0], vv[1]), fmaxf(vv[2], vv[3]));
    #pragma unroll
    for (int o = 1; o < 16; o <<= 1)
        mz = fmaxf(mz, __shfl_xor_sync(0xffffffffu, mz, o));
    float az = ex2f(vv[0]-mz) + ex2f(vv[1]-mz) + ex2f(vv[2]-mz) + ex2f(vv[3]-mz);
    #pragma unroll
    for (int o = 1; o < 16; o <<= 1)
        az += __shfl_xor_sync(0xffffffffu, az, o);

    const float Tst0  = __ldg(&trans[STARTS * NTAGS]);
    const float Tend0 = __ldg(&trans[STOPS]);
    const float Cuni  = Tst0 + (float)(SEQN - 1) * Tend0;
    const float logz  = Cuni + (mz + lg2f(az)) * LN2_F;

    const float* embb = em + (size_t)(blk * GB + cb) * (SEQN * TAGSETN);
    float acc = 0.f; int cnt = 0;
    #pragma unroll 4
    for (int k2 = 0; k2 < 32; ++k2) {
        const int t  = cr + 16 * k2;
        const int tg = stg[cb][t];
        const bool mk2 = (tg != 0);
        cnt += mk2 ? 1 : 0;
        if (t == 0) {
            acc += trans[STARTS * NTAGS + tg];
            if (mk2) acc += embb[tg];
        } else if (mk2) {
            acc += embb[t * TAGSETN + tg] + trans[stg[cb][t-1] * NTAGS + tg];
        }
    }
    #pragma unroll
    for (int o = 1; o < 16; o <<= 1) {
        acc += __shfl_xor_sync(0xffffffffu, acc, o);
        cnt += __shfl_xor_sync(0xffffffffu, cnt, o);
    }
    if (cr == 0) {
        int last = cnt - 1; if (last < 0) last = 0;
        out[blk * GB + cb] = acc + trans[stg[cb][last] * NTAGS + STOPS] - logz;
    }
}

extern "C" void kernel_launch(void* const* d_in, const int* in_sizes, int n_in,
                              void* d_out, int out_size)
{
    const float* emissions   = (const float*)d_in[0];
    const int*   tags        = (const int*)d_in[1];
    const float* transitions = (const float*)d_in[2];
    float*       out         = (float*)d_out;

    const int B = in_sizes[1] / SEQN;
    crf_mma_kernel<<<B / GB, 64>>>(emissions, tags, transitions, out);
}

// round 11
// speedup vs baseline: 1.4614x; 1.4614x over previous
#include <cuda_runtime.h>
#include <cuda_fp16.h>

#define TAGSETN 64
#define SEQN    512
#define MIDT    256
#define NTAGS   66
#define STARTS  64
#define STOPS   65
#define LOG2E_F 1.4426950408889634f
#define LN2_F   0.6931471805599453f
#define OFFB    12.0f

__device__ __forceinline__ float ex2f(float x){float r;asm("ex2.approx.ftz.f32 %0, %1;":"=f"(r):"f"(x));return r;}
__device__ __forceinline__ float lg2f(float x){float r;asm("lg2.approx.ftz.f32 %0, %1;":"=f"(r):"f"(x));return r;}

// two dots sharing one pass over buf: s0 = a.E0, s1 = a.E1
__device__ __forceinline__ void dot2(const __half2* buf,
                                     const __half2* E0, const __half2* E1,
                                     float& s0, float& s1)
{
    const uint4* p4 = (const uint4*)buf;
    const __half2 z = __floats2half2_rn(0.f, 0.f);
    __half2 c0=z,c1=z,c2=z,c3=z, d0=z,d1=z,d2=z,d3=z;
    #pragma unroll
    for (int q = 0; q < 8; ++q) {
        const uint4 u = p4[q];
        const __half2 v0 = *(const __half2*)&u.x;
        const __half2 v1 = *(const __half2*)&u.y;
        const __half2 v2 = *(const __half2*)&u.z;
        const __half2 v3 = *(const __half2*)&u.w;
        c0 = __hfma2(v0, E0[4*q+0], c0);  d0 = __hfma2(v0, E1[4*q+0], d0);
        c1 = __hfma2(v1, E0[4*q+1], c1);  d1 = __hfma2(v1, E1[4*q+1], d1);
        c2 = __hfma2(v2, E0[4*q+2], c2);  d2 = __hfma2(v2, E1[4*q+2], d2);
        c3 = __hfma2(v3, E0[4*q+3], c3);  d3 = __hfma2(v3, E1[4*q+3], d3);
    }
    const float2 f0 = __half22float2(__hadd2(__hadd2(c0,c1), __hadd2(c2,c3)));
    const float2 f1 = __half22float2(__hadd2(__hadd2(d0,d1), __hadd2(d2,d3)));
    s0 = f0.x + f0.y;
    s1 = f1.x + f1.y;
}

__global__ __launch_bounds__(64, 8)
void crf_warp_kernel(const float* __restrict__ em,
                     const int*   __restrict__ tags,
                     const float* __restrict__ trans,
                     float*       __restrict__ out)
{
    const int b   = blockIdx.x;
    const int tid = threadIdx.x;
    const int w   = tid >> 5;           // 0 = forward, 1 = backward
    const int k   = tid & 31;
    const int j0  = 2 * k, j1 = 2 * k + 1;

    __shared__ __align__(16) __half2 bufF[2][32], bufB[2][32];
    __shared__ float lgA[TAGSETN], lgB[TAGSETN];
    __shared__ float csum[2];
    __shared__ int   ccnt;
    __shared__ int   stags[SEQN];

    const float* emb = em + (size_t)b * (SEQN * TAGSETN);

    #pragma unroll
    for (int q = 0; q < SEQN / 64; ++q)
        stags[tid + 64 * q] = tags[b * SEQN + tid + 64 * q];
    __syncthreads();

    __half2 E0[32], E1[32];

    if (w == 0) {
        // ================= FORWARD: alpha_0 .. alpha_256 =================
        #pragma unroll
        for (int r = 0; r < 32; ++r) {
            E0[r] = __floats2half2_rn(__expf(trans[(2*r  )*NTAGS + j0]),
                                      __expf(trans[(2*r+1)*NTAGS + j0]));
            E1[r] = __floats2half2_rn(__expf(trans[(2*r  )*NTAGS + j1]),
                                      __expf(trans[(2*r+1)*NTAGS + j1]));
        }
        const float Tst0 = __ldg(&trans[STARTS * NTAGS]);
        float lb0 = (emb[j0] + trans[STARTS*NTAGS + j0] - Tst0) * LOG2E_F;
        float lb1 = (emb[j1] + trans[STARTS*NTAGS + j1] - Tst0) * LOG2E_F;

        float mx = fmaxf(lb0, lb1);
        #pragma unroll
        for (int o = 16; o; o >>= 1)
            mx = fmaxf(mx, __shfl_xor_sync(0xffffffffu, mx, o));
        float Mprev = mx;
        float a0 = ex2f(lb0 - Mprev), a1 = ex2f(lb1 - Mprev);
        float lb = lb0;                     // only lane 0's matters

        float2 e_c = *(const float2*)(emb + 1*TAGSETN + j0);
        float2 e_1 = *(const float2*)(emb + 2*TAGSETN + j0);
        float2 e_2 = *(const float2*)(emb + 3*TAGSETN + j0);
        float2 pe_c = make_float2(ex2f(e_c.x * LOG2E_F), ex2f(e_c.y * LOG2E_F));
        int tgc = stags[1];

        for (int t = 1; t <= MIDT; ++t) {
            __half2* buf = bufF[t & 1];
            buf[k] = __floats2half2_rn(a0, a1);
            const float Mt = __shfl_sync(0xffffffffu, lb, 0) + OFFB;
            __syncwarp();

            const float hb = ex2f(Mprev - Mt);
            float s0, s1;
            dot2(buf, E0, E1, s0, s1);

            const bool mk = (tgc != 0);
            a0 = mk ? s0 * (pe_c.x * hb) : a0 * hb;
            a1 = mk ? s1 * (pe_c.y * hb) : a1 * hb;
            lb = mk ? (e_c.x * LOG2E_F + Mprev + lg2f(s0)) : lb;
            Mprev = Mt;

            e_c = e_1; e_1 = e_2;
            const int tn = (t + 3 <= MIDT) ? t + 3 : MIDT;
            e_2 = *(const float2*)(emb + tn * TAGSETN + j0);
            pe_c = make_float2(ex2f(e_c.x * LOG2E_F), ex2f(e_c.y * LOG2E_F));
            tgc = stags[(t + 1 <= MIDT) ? t + 1 : MIDT];
        }
        lgA[j0] = lg2f(a0) + Mprev;
        lgA[j1] = lg2f(a1) + Mprev;
    } else {
        // ================= BACKWARD: beta_511 .. beta_256 =================
        #pragma unroll
        for (int r = 0; r < 32; ++r) {
            E0[r] = __floats2half2_rn(__expf(trans[j0*NTAGS + 2*r]),
                                      __expf(trans[j0*NTAGS + 2*r + 1]));
            E1[r] = __floats2half2_rn(__expf(trans[j1*NTAGS + 2*r]),
                                      __expf(trans[j1*NTAGS + 2*r + 1]));
        }
        float lb = 0.f, Mprev = 0.f, a0 = 1.f, a1 = 1.f;

        float2 e_c = *(const float2*)(emb + 511*TAGSETN + j0);
        float2 e_1 = *(const float2*)(emb + 510*TAGSETN + j0);
        float2 e_2 = *(const float2*)(emb + 509*TAGSETN + j0);
        float2 pe_c = make_float2(ex2f(e_c.x * LOG2E_F), ex2f(e_c.y * LOG2E_F));
        int tgc = stags[511];

        for (int t = 511; t >= 257; --t) {
            __half2* buf = bufB[t & 1];
            buf[k] = __floats2half2_rn(a0 * pe_c.x, a1 * pe_c.y);
            const float Mt = __shfl_sync(0xffffffffu, lb, 0) + OFFB;
            __syncwarp();

            const float hb = ex2f(Mprev - Mt);
            float s0, s1;
            dot2(buf, E0, E1, s0, s1);

            const bool mk = (tgc != 0);
            a0 = (mk ? s0 : a0) * hb;
            a1 = (mk ? s1 : a1) * hb;
            lb = mk ? (Mprev + lg2f(s0)) : lb;
            Mprev = Mt;

            e_c = e_1; e_1 = e_2;
            const int tn = (t - 3 >= 257) ? t - 3 : 257;
            e_2 = *(const float2*)(emb + tn * TAGSETN + j0);
            pe_c = make_float2(ex2f(e_c.x * LOG2E_F), ex2f(e_c.y * LOG2E_F));
            tgc = stags[(t - 1 >= 257) ? t - 1 : 257];
        }
        lgB[j0] = lg2f(a0) + Mprev;
        lgB[j1] = lg2f(a1) + Mprev;
    }
    __syncthreads();

    // ================= combine =================
    if (w == 0) {
        const float v0 = lgA[j0] + lgB[j0];
        const float v1 = lgA[j1] + lgB[j1];
        float mz = fmaxf(v0, v1);
        #pragma unroll
        for (int o = 16; o; o >>= 1)
            mz = fmaxf(mz, __shfl_xor_sync(0xffffffffu, mz, o));
        float az = ex2f(v0 - mz) + ex2f(v1 - mz);
        #pragma unroll
        for (int o = 16; o; o >>= 1)
            az += __shfl_xor_sync(0xffffffffu, az, o);
        if (k == 0) csum[0] = mz + lg2f(az);       // base-2 lse
    } else {
        float acc = 0.f; int cnt = 0;
        #pragma unroll 4
        for (int q = 0; q < 16; ++q) {
            const int t  = k + 32 * q;
            const int tg = stags[t];
            const bool mk = (tg != 0);
            cnt += mk ? 1 : 0;
            if (t == 0) {
                acc += trans[STARTS * NTAGS + tg];
                if (mk) acc += emb[tg];
            } else if (mk) {
                acc += emb[t * TAGSETN + tg] + trans[stags[t-1] * NTAGS + tg];
            }
        }
        #pragma unroll
        for (int o = 16; o; o >>= 1) {
            acc += __shfl_xor_sync(0xffffffffu, acc, o);
            cnt += __shfl_xor_sync(0xffffffffu, cnt, o);
        }
        if (k == 0) { csum[1] = acc; ccnt = cnt; }
    }
    __syncthreads();

    if (tid == 0) {
        const float Tst0  = __ldg(&trans[STARTS * NTAGS]);
        const float Tend0 = __ldg(&trans[STOPS]);
        const float Cuni  = Tst0 + (float)(SEQN - 1) * Tend0;
        const float log_z = Cuni + csum[0] * LN2_F;
        int last = ccnt - 1; if (last < 0) last = 0;
        out[b] = csum[1] + trans[stags[last] * NTAGS + STOPS] - log_z;
    }
}

extern "C" void kernel_launch(void* const* d_in, const int* in_sizes, int n_in,
                              void* d_out, int out_size)
{
    const float* emissions   = (const float*)d_in[0];
    const int*   tags        = (const int*)d_in[1];
    const float* transitions = (const float*)d_in[2];
    float*       out         = (float*)d_out;

    const int B = in_sizes[1] / SEQN;
    crf_warp_kernel<<<B, 64>>>(emissions, tags, transitions, out);
}